// round 2
// baseline (speedup 1.0000x reference)
#include <cuda_runtime.h>
#include <cstdint>

// ---------------- problem constants ----------------
#define BATCH 8192
#define INSZ  1024
#define HID   2048
#define NG    6144            // 3*HID
#define KTOT  3072            // INSZ + HID (chunks of 32: 96)
#define KITERS 96
#define STAGES 5

// scratch (static device allocations are allowed)
__device__ float g_BT[(size_t)NG * KTOT];          // [W;Wh]^T packed K-major, tf32-rounded
__device__ float g_gates[(size_t)BATCH * NG];      // gates pre-activations

// ---------------- ptx helpers (family-portable: sm_80/90 era only) ----------------
#define CP_ASYNC16(dst, src) \
    asm volatile("cp.async.cg.shared.global [%0], [%1], 16;" :: "r"(dst), "l"(src))
#define CP_COMMIT() asm volatile("cp.async.commit_group;" ::: "memory")
#define CP_WAIT3()  asm volatile("cp.async.wait_group 3;" ::: "memory")

#define LDSM4(r0, r1, r2, r3, addr) \
    asm volatile("ldmatrix.sync.aligned.m8n8.x4.shared.b16 {%0,%1,%2,%3}, [%4];" \
        : "=r"(r0), "=r"(r1), "=r"(r2), "=r"(r3) : "r"(addr))

#define MMA_TF32(d, a, b) \
    asm volatile("mma.sync.aligned.m16n8k8.row.col.f32.tf32.tf32.f32 " \
        "{%0,%1,%2,%3}, {%4,%5,%6,%7}, {%8,%9}, {%0,%1,%2,%3};" \
        : "+f"((d)[0]), "+f"((d)[1]), "+f"((d)[2]), "+f"((d)[3]) \
        : "r"((a)[0]), "r"((a)[1]), "r"((a)[2]), "r"((a)[3]), \
          "r"((b)[0]), "r"((b)[1]))

// ---------------- kernel 1: pack [W; Wh] -> BT[n][k] (K-major, tf32-rounded) ----------------
__global__ void lstm_pack_bt(const float* __restrict__ W, const float* __restrict__ Wh,
                             float* __restrict__ BT) {
    __shared__ float t[32][33];
    int k0 = blockIdx.x * 32, n0 = blockIdx.y * 32;
    int k = k0 + threadIdx.y, n = n0 + threadIdx.x;
    float v = (k < INSZ) ? W[(size_t)k * NG + n] : Wh[(size_t)(k - INSZ) * NG + n];
    uint32_t r;
    asm("cvt.rna.tf32.f32 %0, %1;" : "=r"(r) : "f"(v));   // RNA pre-round (HW truncates)
    t[threadIdx.y][threadIdx.x] = __uint_as_float(r);
    __syncthreads();
    BT[(size_t)(n0 + threadIdx.y) * KTOT + k0 + threadIdx.x] = t[threadIdx.x][threadIdx.y];
}

// ---------------- kernel 2: tf32 mma.sync GEMM, gates = [X|H] @ BT^T ----------------
// CTA tile 128(M) x 128(N), K-chunk 32. 8 warps, warp tile 32(M) x 64(N).
// smem per stage: A 128x32 f32 (16KB) + B 128x32 f32 (16KB); XOR-swizzled 16B chunks.
__global__ void __launch_bounds__(256) lstm_gemm(
    const float* __restrict__ X, const float* __restrict__ H,
    const float* __restrict__ BT, float* __restrict__ gates) {
    extern __shared__ float smem[];
    const int tid = threadIdx.x;
    const int lane = tid & 31, wid = tid >> 5;
    const int wm = wid & 3, wn = wid >> 2;            // 4x2 warp grid
    const int m0 = blockIdx.y * 128, n0 = blockIdx.x * 128;

    const uint32_t sbase = (uint32_t)__cvta_generic_to_shared(smem);

    float acc[2][8][4];
    #pragma unroll
    for (int i = 0; i < 2; i++)
        #pragma unroll
        for (int j = 0; j < 8; j++)
            #pragma unroll
            for (int k = 0; k < 4; k++) acc[i][j][k] = 0.f;

    // per-lane ldmatrix row roles
    const int a_moff = ((lane >> 3) & 1) * 8 + (lane & 7);   // row within 16-row mblock
    const int a_csel = lane >> 4;                            // 0/1: k-half
    const int b_noff = ((lane >> 4) & 1) * 8 + (lane & 7);   // row within 16-row nb-pair
    const int b_csel = (lane >> 3) & 1;

    auto load_stage = [&](int kc, int s) {
        float* As = smem + s * 8192;
        float* Bs = As + 4096;
        const float* aptr;
        int lda, acol;
        if (kc < INSZ / 32) { aptr = X; lda = INSZ; acol = kc * 32; }
        else                { aptr = H; lda = HID;  acol = (kc - INSZ / 32) * 32; }
        #pragma unroll
        for (int i = 0; i < 4; i++) {
            int ch = tid + i * 256;                    // 0..1023
            int m = ch >> 3, c = ch & 7;
            const float* src = aptr + (size_t)(m0 + m) * lda + acol + c * 4;
            uint32_t dst = (uint32_t)__cvta_generic_to_shared(As + m * 32 + ((c ^ (m & 7)) << 2));
            CP_ASYNC16(dst, src);
        }
        #pragma unroll
        for (int i = 0; i < 4; i++) {
            int ch = tid + i * 256;
            int n = ch >> 3, c = ch & 7;
            const float* src = BT + (size_t)(n0 + n) * KTOT + kc * 32 + c * 4;
            uint32_t dst = (uint32_t)__cvta_generic_to_shared(Bs + n * 32 + ((c ^ (n & 7)) << 2));
            CP_ASYNC16(dst, src);
        }
    };

    auto compute_stage = [&](int s) {
        const uint32_t As = sbase + s * 32768;
        const uint32_t Bs = As + 16384;
        #pragma unroll
        for (int kk = 0; kk < 4; kk++) {
            uint32_t a[2][4];
            #pragma unroll
            for (int mb = 0; mb < 2; mb++) {
                int m = wm * 32 + mb * 16 + a_moff;
                int c = kk * 2 + a_csel;
                uint32_t addr = As + m * 128 + ((c ^ (m & 7)) << 4);
                LDSM4(a[mb][0], a[mb][1], a[mb][2], a[mb][3], addr);
            }
            uint32_t b[8][2];
            #pragma unroll
            for (int p = 0; p < 4; p++) {
                int n = wn * 64 + p * 16 + b_noff;
                int c = kk * 2 + b_csel;
                uint32_t addr = Bs + n * 128 + ((c ^ (n & 7)) << 4);
                LDSM4(b[2 * p][0], b[2 * p][1], b[2 * p + 1][0], b[2 * p + 1][1], addr);
            }
            #pragma unroll
            for (int mb = 0; mb < 2; mb++)
                #pragma unroll
                for (int nb = 0; nb < 8; nb++)
                    MMA_TF32(acc[mb][nb], a[mb], b[nb]);
        }
    };

    // prologue: fill 4 of 5 stages
    #pragma unroll
    for (int s = 0; s < STAGES - 1; s++) { load_stage(s, s); CP_COMMIT(); }

    for (int kc = 0; kc < KITERS; kc++) {
        CP_WAIT3();
        __syncthreads();
        int ls = kc + STAGES - 1;
        if (ls < KITERS) load_stage(ls, ls % STAGES);
        CP_COMMIT();                                   // commit (possibly empty) group
        compute_stage(kc % STAGES);
    }

    // write accumulators to gates scratch
    const int g = lane >> 2, tig = lane & 3;
    #pragma unroll
    for (int mb = 0; mb < 2; mb++) {
        #pragma unroll
        for (int nb = 0; nb < 8; nb++) {
            int row = m0 + wm * 32 + mb * 16 + g;
            int col = n0 + wn * 64 + nb * 8 + tig * 2;
            float2 v0 = make_float2(acc[mb][nb][0], acc[mb][nb][1]);
            float2 v1 = make_float2(acc[mb][nb][2], acc[mb][nb][3]);
            *(float2*)(gates + (size_t)row * NG + col) = v0;
            *(float2*)(gates + (size_t)(row + 8) * NG + col) = v1;
        }
    }
}

// ---------------- kernel 3: LSTM epilogue ----------------
__device__ __forceinline__ float fast_sigmoid(float x) {
    return __fdividef(1.f, 1.f + __expf(-x));
}
__device__ __forceinline__ float fast_tanh(float x) {
    return __fdividef(2.f, 1.f + __expf(-2.f * x)) - 1.f;
}

__global__ void lstm_epilogue(const float* __restrict__ gates, const float* __restrict__ c0,
                              const float* __restrict__ bias, float* __restrict__ out) {
    int t = blockIdx.x * blockDim.x + threadIdx.x;    // one float4 along n
    int n = (t & 511) * 4;                            // HID/4 = 512
    int m = t >> 9;
    const float4 f4 = *(const float4*)(gates + (size_t)m * NG + n);
    const float4 i4 = *(const float4*)(gates + (size_t)m * NG + HID + n);
    const float4 g4 = *(const float4*)(gates + (size_t)m * NG + 2 * HID + n);
    const float4 c4 = *(const float4*)(c0 + (size_t)m * HID + n);
    const float4 bf = *(const float4*)(bias + n);
    const float4 bi = *(const float4*)(bias + HID + n);
    const float4 bc = *(const float4*)(bias + 2 * HID + n);
    float4 o;
    o.x = fast_sigmoid(f4.x + bf.x) * c4.x + fast_sigmoid(i4.x + bi.x) * fast_tanh(g4.x + bc.x);
    o.y = fast_sigmoid(f4.y + bf.y) * c4.y + fast_sigmoid(i4.y + bi.y) * fast_tanh(g4.y + bc.y);
    o.z = fast_sigmoid(f4.z + bf.z) * c4.z + fast_sigmoid(i4.z + bi.z) * fast_tanh(g4.z + bc.z);
    o.w = fast_sigmoid(f4.w + bf.w) * c4.w + fast_sigmoid(i4.w + bi.w) * fast_tanh(g4.w + bc.w);
    *(float4*)(out + (size_t)m * HID + n) = o;
}

// ---------------- host launch ----------------
extern "C" void kernel_launch(void* const* d_in, const int* in_sizes, int n_in,
                              void* d_out, int out_size) {
    const float* X    = (const float*)d_in[0];
    const float* H0   = (const float*)d_in[1];
    const float* C0   = (const float*)d_in[2];
    const float* W    = (const float*)d_in[3];
    const float* Wh   = (const float*)d_in[4];
    const float* Bias = (const float*)d_in[5];
    float* out = (float*)d_out;

    float* bt = nullptr;
    float* gates = nullptr;
    cudaGetSymbolAddress((void**)&bt, g_BT);
    cudaGetSymbolAddress((void**)&gates, g_gates);

    static bool attr_set = false;
    cudaFuncSetAttribute(lstm_gemm, cudaFuncAttributeMaxDynamicSharedMemorySize,
                         STAGES * 32768);
    (void)attr_set;

    lstm_pack_bt<<<dim3(KTOT / 32, NG / 32), dim3(32, 32)>>>(W, Wh, bt);
    lstm_gemm<<<dim3(NG / 128, BATCH / 128), 256, STAGES * 32768>>>(X, H0, bt, gates);
    lstm_epilogue<<<(BATCH * HID / 4) / 256, 256>>>(gates, C0, Bias, out);
}

// round 3
// speedup vs baseline: 1.1170x; 1.1170x over previous
#include <cuda_runtime.h>
#include <cstdint>

// ---------------- problem constants ----------------
#define BATCH 8192
#define INSZ  1024
#define HID   2048
#define NG    6144            // 3*HID
#define KTOT  3072            // INSZ + HID
#define KITERS 96
#define STAGES 4

// CTA tile 256(M) x 128(N), warp tile 64x64, 8 warps (4x2)
#define STAGE_FLOATS 12288     // A 256x32 (8192) + B 128x32 (4096)
#define SMEM_TOTAL (STAGES * STAGE_FLOATS * 4)   // 196608

// scratch (static device arrays are allowed)
__device__ float g_BT[(size_t)NG * KTOT];          // [W;Wh]^T K-major, tf32-rounded
__device__ float g_gates[(size_t)BATCH * NG];      // gate pre-activations

// ---------------- ptx helpers ----------------
#define CP_ASYNC16(dst, src) \
    asm volatile("cp.async.cg.shared.global [%0], [%1], 16;" :: "r"(dst), "l"(src))
#define CP_COMMIT() asm volatile("cp.async.commit_group;" ::: "memory")
#define CP_WAIT2()  asm volatile("cp.async.wait_group 2;" ::: "memory")

#define LDSM4(r0, r1, r2, r3, addr) \
    asm volatile("ldmatrix.sync.aligned.m8n8.x4.shared.b16 {%0,%1,%2,%3}, [%4];" \
        : "=r"(r0), "=r"(r1), "=r"(r2), "=r"(r3) : "r"(addr))

#define MMA_TF32(d, a, b) \
    asm volatile("mma.sync.aligned.m16n8k8.row.col.f32.tf32.tf32.f32 " \
        "{%0,%1,%2,%3}, {%4,%5,%6,%7}, {%8,%9}, {%0,%1,%2,%3};" \
        : "+f"((d)[0]), "+f"((d)[1]), "+f"((d)[2]), "+f"((d)[3]) \
        : "r"((a)[0]), "r"((a)[1]), "r"((a)[2]), "r"((a)[3]), \
          "r"((b)[0]), "r"((b)[1]))

// ---------------- kernel 1: pack [W; Wh] -> BT[n][k] (K-major, tf32-rounded) ----------------
// Tile: 32(k) x 128(n). 256 threads. float4 loads along n, float4 stores along k.
__global__ void __launch_bounds__(256) lstm_pack_bt(
    const float* __restrict__ W, const float* __restrict__ Wh, float* __restrict__ BT) {
    __shared__ float s[32 * 129];
    const int tid = threadIdx.x;
    const int k0 = blockIdx.x * 32, n0 = blockIdx.y * 128;

    #pragma unroll
    for (int i = 0; i < 4; i++) {
        int idx = tid + i * 256;          // 0..1023
        int r = idx >> 5;                 // k row 0..31
        int c4 = idx & 31;                // float4 col
        int k = k0 + r;
        const float* src = (k < INSZ) ? (W + (size_t)k * NG + n0 + c4 * 4)
                                      : (Wh + (size_t)(k - INSZ) * NG + n0 + c4 * 4);
        float4 v = *(const float4*)src;
        uint32_t rr;
        asm("cvt.rna.tf32.f32 %0, %1;" : "=r"(rr) : "f"(v.x)); v.x = __uint_as_float(rr);
        asm("cvt.rna.tf32.f32 %0, %1;" : "=r"(rr) : "f"(v.y)); v.y = __uint_as_float(rr);
        asm("cvt.rna.tf32.f32 %0, %1;" : "=r"(rr) : "f"(v.z)); v.z = __uint_as_float(rr);
        asm("cvt.rna.tf32.f32 %0, %1;" : "=r"(rr) : "f"(v.w)); v.w = __uint_as_float(rr);
        s[r * 129 + c4 * 4 + 0] = v.x;
        s[r * 129 + c4 * 4 + 1] = v.y;
        s[r * 129 + c4 * 4 + 2] = v.z;
        s[r * 129 + c4 * 4 + 3] = v.w;
    }
    __syncthreads();
    #pragma unroll
    for (int i = 0; i < 4; i++) {
        int idx = tid + i * 256;          // 0..1023
        int n = idx >> 3;                 // 0..127
        int kg = idx & 7;                 // float4 group along k
        float4 v;
        v.x = s[(kg * 4 + 0) * 129 + n];
        v.y = s[(kg * 4 + 1) * 129 + n];
        v.z = s[(kg * 4 + 2) * 129 + n];
        v.w = s[(kg * 4 + 3) * 129 + n];
        *(float4*)(BT + (size_t)(n0 + n) * KTOT + k0 + kg * 4) = v;
    }
}

// ---------------- kernel 2: tf32 mma.sync GEMM ----------------
__global__ void __launch_bounds__(256, 1) lstm_gemm(
    const float* __restrict__ X, const float* __restrict__ H,
    const float* __restrict__ BT, float* __restrict__ gates) {
    extern __shared__ float smem[];
    const int tid = threadIdx.x;
    const int lane = tid & 31, wid = tid >> 5;
    const int wm = wid & 3, wn = wid >> 2;            // 4x2 warp grid
    const int m0 = blockIdx.y * 256, n0 = blockIdx.x * 128;

    const uint32_t sbase = (uint32_t)__cvta_generic_to_shared(smem);

    float acc[4][8][4];
    #pragma unroll
    for (int i = 0; i < 4; i++)
        #pragma unroll
        for (int j = 0; j < 8; j++)
            #pragma unroll
            for (int k = 0; k < 4; k++) acc[i][j][k] = 0.f;

    const int a_moff = ((lane >> 3) & 1) * 8 + (lane & 7);
    const int a_csel = lane >> 4;
    const int b_noff = ((lane >> 4) & 1) * 8 + (lane & 7);
    const int b_csel = (lane >> 3) & 1;

    auto load_stage = [&](int kc, int s) {
        float* As = smem + s * STAGE_FLOATS;
        float* Bs = As + 8192;
        const float* aptr;
        int lda, acol;
        if (kc < INSZ / 32) { aptr = X; lda = INSZ; acol = kc * 32; }
        else                { aptr = H; lda = HID;  acol = (kc - INSZ / 32) * 32; }
        #pragma unroll
        for (int i = 0; i < 8; i++) {
            int ch = tid + i * 256;                    // 0..2047
            int m = ch >> 3, c = ch & 7;
            const float* src = aptr + (size_t)(m0 + m) * lda + acol + c * 4;
            uint32_t dst = (uint32_t)__cvta_generic_to_shared(As + m * 32 + ((c ^ (m & 7)) << 2));
            CP_ASYNC16(dst, src);
        }
        #pragma unroll
        for (int i = 0; i < 4; i++) {
            int ch = tid + i * 256;                    // 0..1023
            int n = ch >> 3, c = ch & 7;
            const float* src = BT + (size_t)(n0 + n) * KTOT + kc * 32 + c * 4;
            uint32_t dst = (uint32_t)__cvta_generic_to_shared(Bs + n * 32 + ((c ^ (n & 7)) << 2));
            CP_ASYNC16(dst, src);
        }
    };

    auto compute_stage = [&](int s) {
        const uint32_t As = sbase + s * (STAGE_FLOATS * 4);
        const uint32_t Bs = As + 32768;
        #pragma unroll
        for (int kk = 0; kk < 4; kk++) {
            uint32_t a[4][4];
            #pragma unroll
            for (int mb = 0; mb < 4; mb++) {
                int m = wm * 64 + mb * 16 + a_moff;
                int c = kk * 2 + a_csel;
                uint32_t addr = As + m * 128 + ((c ^ (m & 7)) << 4);
                LDSM4(a[mb][0], a[mb][1], a[mb][2], a[mb][3], addr);
            }
            uint32_t b[8][2];
            #pragma unroll
            for (int p = 0; p < 4; p++) {
                int n = wn * 64 + p * 16 + b_noff;
                int c = kk * 2 + b_csel;
                uint32_t addr = Bs + n * 128 + ((c ^ (n & 7)) << 4);
                LDSM4(b[2 * p][0], b[2 * p][1], b[2 * p + 1][0], b[2 * p + 1][1], addr);
            }
            #pragma unroll
            for (int mb = 0; mb < 4; mb++)
                #pragma unroll
                for (int nb = 0; nb < 8; nb++)
                    MMA_TF32(acc[mb][nb], a[mb], b[nb]);
        }
    };

    // prologue: fill 3 of 4 stages
    #pragma unroll
    for (int s = 0; s < STAGES - 1; s++) { load_stage(s, s); CP_COMMIT(); }

    for (int kc = 0; kc < KITERS; kc++) {
        CP_WAIT2();
        __syncthreads();
        int ls = kc + STAGES - 1;
        if (ls < KITERS) load_stage(ls, ls & 3);
        CP_COMMIT();
        compute_stage(kc & 3);
    }

    // write accumulators to gates scratch
    const int g = lane >> 2, tig = lane & 3;
    #pragma unroll
    for (int mb = 0; mb < 4; mb++) {
        #pragma unroll
        for (int nb = 0; nb < 8; nb++) {
            int row = m0 + wm * 64 + mb * 16 + g;
            int col = n0 + wn * 64 + nb * 8 + tig * 2;
            *(float2*)(gates + (size_t)row * NG + col) =
                make_float2(acc[mb][nb][0], acc[mb][nb][1]);
            *(float2*)(gates + (size_t)(row + 8) * NG + col) =
                make_float2(acc[mb][nb][2], acc[mb][nb][3]);
        }
    }
}

// ---------------- kernel 3: LSTM epilogue ----------------
__device__ __forceinline__ float fast_sigmoid(float x) {
    return __fdividef(1.f, 1.f + __expf(-x));
}
__device__ __forceinline__ float fast_tanh(float x) {
    return __fdividef(2.f, 1.f + __expf(-2.f * x)) - 1.f;
}

__global__ void lstm_epilogue(const float* __restrict__ gates, const float* __restrict__ c0,
                              const float* __restrict__ bias, float* __restrict__ out) {
    int t = blockIdx.x * blockDim.x + threadIdx.x;    // one float4 along n
    int n = (t & 511) * 4;                            // HID/4 = 512
    int m = t >> 9;
    const float4 f4 = *(const float4*)(gates + (size_t)m * NG + n);
    const float4 i4 = *(const float4*)(gates + (size_t)m * NG + HID + n);
    const float4 g4 = *(const float4*)(gates + (size_t)m * NG + 2 * HID + n);
    const float4 c4 = *(const float4*)(c0 + (size_t)m * HID + n);
    const float4 bf = *(const float4*)(bias + n);
    const float4 bi = *(const float4*)(bias + HID + n);
    const float4 bc = *(const float4*)(bias + 2 * HID + n);
    float4 o;
    o.x = fast_sigmoid(f4.x + bf.x) * c4.x + fast_sigmoid(i4.x + bi.x) * fast_tanh(g4.x + bc.x);
    o.y = fast_sigmoid(f4.y + bf.y) * c4.y + fast_sigmoid(i4.y + bi.y) * fast_tanh(g4.y + bc.y);
    o.z = fast_sigmoid(f4.z + bf.z) * c4.z + fast_sigmoid(i4.z + bi.z) * fast_tanh(g4.z + bc.z);
    o.w = fast_sigmoid(f4.w + bf.w) * c4.w + fast_sigmoid(i4.w + bi.w) * fast_tanh(g4.w + bc.w);
    *(float4*)(out + (size_t)m * HID + n) = o;
}

// ---------------- host launch ----------------
extern "C" void kernel_launch(void* const* d_in, const int* in_sizes, int n_in,
                              void* d_out, int out_size) {
    const float* X    = (const float*)d_in[0];
    const float* H0   = (const float*)d_in[1];
    const float* C0   = (const float*)d_in[2];
    const float* W    = (const float*)d_in[3];
    const float* Wh   = (const float*)d_in[4];
    const float* Bias = (const float*)d_in[5];
    float* out = (float*)d_out;

    float* bt = nullptr;
    float* gates = nullptr;
    cudaGetSymbolAddress((void**)&bt, g_BT);
    cudaGetSymbolAddress((void**)&gates, g_gates);

    cudaFuncSetAttribute(lstm_gemm, cudaFuncAttributeMaxDynamicSharedMemorySize, SMEM_TOTAL);

    lstm_pack_bt<<<dim3(KTOT / 32, NG / 128), 256>>>(W, Wh, bt);
    lstm_gemm<<<dim3(NG / 128, BATCH / 256), 256, SMEM_TOTAL>>>(X, H0, bt, gates);
    lstm_epilogue<<<(BATCH * HID / 4) / 256, 256>>>(gates, C0, Bias, out);
}

// round 4
// speedup vs baseline: 1.2475x; 1.1169x over previous
#include <cuda_runtime.h>
#include <cstdint>

// ---------------- problem constants ----------------
#define BATCH 8192
#define INSZ  1024
#define HID   2048
#define NG    6144            // 3*HID
#define KTOT  3072            // INSZ + HID
#define KITERS 96
#define STAGES 3

// CTA tile 128(M) x 128(N), warp tile 64x64, 4 warps (2x2), 2 CTAs/SM
#define STAGE_FLOATS 8192      // A 128x32 (4096) + B 128x32 (4096)
#define STAGE_BYTES  32768
#define SMEM_TOTAL (STAGES * STAGE_BYTES)   // 98304 per CTA

// scratch (static device arrays are allowed)
__device__ float g_BT[(size_t)NG * KTOT];          // [W;Wh]^T K-major, tf32-rounded
__device__ float g_gates[(size_t)BATCH * NG];      // gate pre-activations

// ---------------- ptx helpers ----------------
#define CP_ASYNC16(dst, src) \
    asm volatile("cp.async.cg.shared.global [%0], [%1], 16;" :: "r"(dst), "l"(src))
#define CP_COMMIT() asm volatile("cp.async.commit_group;" ::: "memory")
#define CP_WAIT1()  asm volatile("cp.async.wait_group 1;" ::: "memory")

#define LDSM4(r0, r1, r2, r3, addr) \
    asm volatile("ldmatrix.sync.aligned.m8n8.x4.shared.b16 {%0,%1,%2,%3}, [%4];" \
        : "=r"(r0), "=r"(r1), "=r"(r2), "=r"(r3) : "r"(addr))

#define MMA_TF32(d, a, b) \
    asm volatile("mma.sync.aligned.m16n8k8.row.col.f32.tf32.tf32.f32 " \
        "{%0,%1,%2,%3}, {%4,%5,%6,%7}, {%8,%9}, {%0,%1,%2,%3};" \
        : "+f"((d)[0]), "+f"((d)[1]), "+f"((d)[2]), "+f"((d)[3]) \
        : "r"((a)[0]), "r"((a)[1]), "r"((a)[2]), "r"((a)[3]), \
          "r"((b)[0]), "r"((b)[1]))

// ---------------- kernel 1: pack [W; Wh] -> BT[n][k] (K-major, tf32-rounded) ----------------
__global__ void __launch_bounds__(256) lstm_pack_bt(
    const float* __restrict__ W, const float* __restrict__ Wh, float* __restrict__ BT) {
    __shared__ float s[32 * 129];
    const int tid = threadIdx.x;
    const int k0 = blockIdx.x * 32, n0 = blockIdx.y * 128;

    #pragma unroll
    for (int i = 0; i < 4; i++) {
        int idx = tid + i * 256;
        int r = idx >> 5;
        int c4 = idx & 31;
        int k = k0 + r;
        const float* src = (k < INSZ) ? (W + (size_t)k * NG + n0 + c4 * 4)
                                      : (Wh + (size_t)(k - INSZ) * NG + n0 + c4 * 4);
        float4 v = *(const float4*)src;
        uint32_t rr;
        asm("cvt.rna.tf32.f32 %0, %1;" : "=r"(rr) : "f"(v.x)); v.x = __uint_as_float(rr);
        asm("cvt.rna.tf32.f32 %0, %1;" : "=r"(rr) : "f"(v.y)); v.y = __uint_as_float(rr);
        asm("cvt.rna.tf32.f32 %0, %1;" : "=r"(rr) : "f"(v.z)); v.z = __uint_as_float(rr);
        asm("cvt.rna.tf32.f32 %0, %1;" : "=r"(rr) : "f"(v.w)); v.w = __uint_as_float(rr);
        s[r * 129 + c4 * 4 + 0] = v.x;
        s[r * 129 + c4 * 4 + 1] = v.y;
        s[r * 129 + c4 * 4 + 2] = v.z;
        s[r * 129 + c4 * 4 + 3] = v.w;
    }
    __syncthreads();
    #pragma unroll
    for (int i = 0; i < 4; i++) {
        int idx = tid + i * 256;
        int n = idx >> 3;
        int kg = idx & 7;
        float4 v;
        v.x = s[(kg * 4 + 0) * 129 + n];
        v.y = s[(kg * 4 + 1) * 129 + n];
        v.z = s[(kg * 4 + 2) * 129 + n];
        v.w = s[(kg * 4 + 3) * 129 + n];
        *(float4*)(BT + (size_t)(n0 + n) * KTOT + k0 + kg * 4) = v;
    }
}

// ---------------- kernel 2: tf32 mma.sync GEMM, 2 CTAs/SM ----------------
__global__ void __launch_bounds__(128, 2) lstm_gemm(
    const float* __restrict__ X, const float* __restrict__ H,
    const float* __restrict__ BT, float* __restrict__ gates) {
    extern __shared__ float smem[];
    const int tid = threadIdx.x;
    const int lane = tid & 31, wid = tid >> 5;
    const int wm = wid & 1, wn = wid >> 1;            // 2x2 warp grid, warp tile 64x64
    const int m0 = blockIdx.y * 128, n0 = blockIdx.x * 128;

    const uint32_t sbase = (uint32_t)__cvta_generic_to_shared(smem);

    float acc[4][8][4];
    #pragma unroll
    for (int i = 0; i < 4; i++)
        #pragma unroll
        for (int j = 0; j < 8; j++)
            #pragma unroll
            for (int k = 0; k < 4; k++) acc[i][j][k] = 0.f;

    const int a_moff = ((lane >> 3) & 1) * 8 + (lane & 7);
    const int a_csel = lane >> 4;
    const int b_noff = ((lane >> 4) & 1) * 8 + (lane & 7);
    const int b_csel = (lane >> 3) & 1;

    auto load_stage = [&](int kc, int s) {
        float* As = smem + s * STAGE_FLOATS;
        float* Bs = As + 4096;
        const float* aptr;
        int lda, acol;
        if (kc < INSZ / 32) { aptr = X; lda = INSZ; acol = kc * 32; }
        else                { aptr = H; lda = HID;  acol = (kc - INSZ / 32) * 32; }
        #pragma unroll
        for (int i = 0; i < 8; i++) {
            int ch = tid + i * 128;                    // 0..1023
            int m = ch >> 3, c = ch & 7;
            const float* src = aptr + (size_t)(m0 + m) * lda + acol + c * 4;
            uint32_t dst = (uint32_t)__cvta_generic_to_shared(As + m * 32 + ((c ^ (m & 7)) << 2));
            CP_ASYNC16(dst, src);
        }
        #pragma unroll
        for (int i = 0; i < 8; i++) {
            int ch = tid + i * 128;
            int n = ch >> 3, c = ch & 7;
            const float* src = BT + (size_t)(n0 + n) * KTOT + kc * 32 + c * 4;
            uint32_t dst = (uint32_t)__cvta_generic_to_shared(Bs + n * 32 + ((c ^ (n & 7)) << 2));
            CP_ASYNC16(dst, src);
        }
    };

    // fragment loaders (double-buffered across kk)
    auto load_afrag = [&](uint32_t As, int kk, uint32_t a[4][4]) {
        #pragma unroll
        for (int mb = 0; mb < 4; mb++) {
            int m = wm * 64 + mb * 16 + a_moff;
            int c = kk * 2 + a_csel;
            uint32_t addr = As + m * 128 + ((c ^ (m & 7)) << 4);
            LDSM4(a[mb][0], a[mb][1], a[mb][2], a[mb][3], addr);
        }
    };
    auto load_bfrag = [&](uint32_t Bs, int kk, uint32_t b[8][2]) {
        #pragma unroll
        for (int p = 0; p < 4; p++) {
            int n = wn * 64 + p * 16 + b_noff;
            int c = kk * 2 + b_csel;
            uint32_t addr = Bs + n * 128 + ((c ^ (n & 7)) << 4);
            LDSM4(b[2 * p][0], b[2 * p][1], b[2 * p + 1][0], b[2 * p + 1][1], addr);
        }
    };

    // prologue: fill 2 of 3 stages
    #pragma unroll
    for (int s = 0; s < STAGES - 1; s++) { load_stage(s, s); CP_COMMIT(); }

    uint32_t afr[2][4][4], bfr[2][8][2];

    for (int kc = 0; kc < KITERS; kc++) {
        CP_WAIT1();
        __syncthreads();
        int ls = kc + STAGES - 1;
        if (ls < KITERS) load_stage(ls, ls % STAGES);
        CP_COMMIT();

        const uint32_t As = sbase + (kc % STAGES) * STAGE_BYTES;
        const uint32_t Bs = As + 16384;

        load_afrag(As, 0, afr[0]);
        load_bfrag(Bs, 0, bfr[0]);
        #pragma unroll
        for (int kk = 0; kk < 4; kk++) {
            int cur = kk & 1, nxt = cur ^ 1;
            if (kk < 3) {
                load_afrag(As, kk + 1, afr[nxt]);
                load_bfrag(Bs, kk + 1, bfr[nxt]);
            }
            #pragma unroll
            for (int mb = 0; mb < 4; mb++)
                #pragma unroll
                for (int nb = 0; nb < 8; nb++)
                    MMA_TF32(acc[mb][nb], afr[cur][mb], bfr[cur][nb]);
        }
    }

    // write accumulators to gates scratch
    const int g = lane >> 2, tig = lane & 3;
    #pragma unroll
    for (int mb = 0; mb < 4; mb++) {
        #pragma unroll
        for (int nb = 0; nb < 8; nb++) {
            int row = m0 + wm * 64 + mb * 16 + g;
            int col = n0 + wn * 64 + nb * 8 + tig * 2;
            *(float2*)(gates + (size_t)row * NG + col) =
                make_float2(acc[mb][nb][0], acc[mb][nb][1]);
            *(float2*)(gates + (size_t)(row + 8) * NG + col) =
                make_float2(acc[mb][nb][2], acc[mb][nb][3]);
        }
    }
}

// ---------------- kernel 3: LSTM epilogue ----------------
__device__ __forceinline__ float fast_sigmoid(float x) {
    return __fdividef(1.f, 1.f + __expf(-x));
}
__device__ __forceinline__ float fast_tanh(float x) {
    return __fdividef(2.f, 1.f + __expf(-2.f * x)) - 1.f;
}

__global__ void lstm_epilogue(const float* __restrict__ gates, const float* __restrict__ c0,
                              const float* __restrict__ bias, float* __restrict__ out) {
    int t = blockIdx.x * blockDim.x + threadIdx.x;
    int n = (t & 511) * 4;
    int m = t >> 9;
    const float4 f4 = *(const float4*)(gates + (size_t)m * NG + n);
    const float4 i4 = *(const float4*)(gates + (size_t)m * NG + HID + n);
    const float4 g4 = *(const float4*)(gates + (size_t)m * NG + 2 * HID + n);
    const float4 c4 = *(const float4*)(c0 + (size_t)m * HID + n);
    const float4 bf = *(const float4*)(bias + n);
    const float4 bi = *(const float4*)(bias + HID + n);
    const float4 bc = *(const float4*)(bias + 2 * HID + n);
    float4 o;
    o.x = fast_sigmoid(f4.x + bf.x) * c4.x + fast_sigmoid(i4.x + bi.x) * fast_tanh(g4.x + bc.x);
    o.y = fast_sigmoid(f4.y + bf.y) * c4.y + fast_sigmoid(i4.y + bi.y) * fast_tanh(g4.y + bc.y);
    o.z = fast_sigmoid(f4.z + bf.z) * c4.z + fast_sigmoid(i4.z + bi.z) * fast_tanh(g4.z + bc.z);
    o.w = fast_sigmoid(f4.w + bf.w) * c4.w + fast_sigmoid(i4.w + bi.w) * fast_tanh(g4.w + bc.w);
    *(float4*)(out + (size_t)m * HID + n) = o;
}

// ---------------- host launch ----------------
extern "C" void kernel_launch(void* const* d_in, const int* in_sizes, int n_in,
                              void* d_out, int out_size) {
    const float* X    = (const float*)d_in[0];
    const float* H0   = (const float*)d_in[1];
    const float* C0   = (const float*)d_in[2];
    const float* W    = (const float*)d_in[3];
    const float* Wh   = (const float*)d_in[4];
    const float* Bias = (const float*)d_in[5];
    float* out = (float*)d_out;

    float* bt = nullptr;
    float* gates = nullptr;
    cudaGetSymbolAddress((void**)&bt, g_BT);
    cudaGetSymbolAddress((void**)&gates, g_gates);

    cudaFuncSetAttribute(lstm_gemm, cudaFuncAttributeMaxDynamicSharedMemorySize, SMEM_TOTAL);

    lstm_pack_bt<<<dim3(KTOT / 32, NG / 128), 256>>>(W, Wh, bt);
    lstm_gemm<<<dim3(NG / 128, BATCH / 128), 128, SMEM_TOTAL>>>(X, H0, bt, gates);
    lstm_epilogue<<<(BATCH * HID / 4) / 256, 256>>>(gates, C0, Bias, out);
}